// round 3
// baseline (speedup 1.0000x reference)
#include <cuda_runtime.h>
#include <cstdint>

// inputs [64,2048,64] fp32 -> flat [131072,64]; codebook [1024,64] fp32.
#define N_ROWS   131072
#define D        64
#define K_CODES  1024
#define TILE     128
#define BLK      128
#define NBLK     (N_ROWS / BLK)      // 1024

// Output: quantized_ste (8388608) | loss (1) | encoding_indices (131072), all fp32
#define LOSS_OFF 8388608
#define IDX_OFF  8388609

__device__ float g_cbT[D * K_CODES];   // transposed codebook [k][j]
__device__ float g_C[K_CODES];         // ||c_j||^2, reference rounding
__device__ float g_blocksum[NBLK];

// fma.rn.f32x2: two independent exact IEEE fp32 FMAs per issue (lo/hi lanes).
__device__ __forceinline__ unsigned long long ffma2(unsigned long long a,
                                                    unsigned long long b,
                                                    unsigned long long c) {
    unsigned long long d;
    asm("fma.rn.f32x2 %0, %1, %2, %3;" : "=l"(d) : "l"(a), "l"(b), "l"(c));
    return d;
}
__device__ __forceinline__ unsigned long long dup2(float x) {
    unsigned long long d;
    asm("mov.b64 %0, {%1, %1};" : "=l"(d) : "f"(x));
    return d;
}
__device__ __forceinline__ void unpack2(unsigned long long v, float& lo, float& hi) {
    asm("mov.b64 {%0, %1}, %2;" : "=f"(lo), "=f"(hi) : "l"(v));
}

// ---- kernel 1: transpose codebook + ||c||^2 with reference rounding ----
// C_j = sequential over k of add(C, mul(c,c))  (separate mul/add, ascending k)
__global__ void vq_prep(const float* __restrict__ cb) {
    int j = blockIdx.x * blockDim.x + threadIdx.x;
    if (j < K_CODES) {
        float s = 0.f;
        #pragma unroll
        for (int k = 0; k < D; k++) {
            float c = cb[j * D + k];
            s = __fadd_rn(s, __fmul_rn(c, c));
            g_cbT[k * K_CODES + j] = c;
        }
        g_C[j] = s;
    }
}

// ---- kernel 2: main VQ, one row per thread, sequential-k exact replication ----
__global__ void __launch_bounds__(BLK) vq_main(const float* __restrict__ inp,
                                               const float* __restrict__ cb,
                                               float* __restrict__ d_out) {
    __shared__ __align__(16) float sCT[D * TILE];   // 32 KB, layout [k][j]
    __shared__ float sC2[TILE];
    __shared__ float sRed[BLK];

    const int row = blockIdx.x * BLK + threadIdx.x;

    // Row x in registers.
    float x[D];
    {
        const float4* xr = (const float4*)(inp + (size_t)row * D);
        #pragma unroll
        for (int i = 0; i < 16; i++) {
            float4 v = xr[i];
            x[4 * i] = v.x; x[4 * i + 1] = v.y; x[4 * i + 2] = v.z; x[4 * i + 3] = v.w;
        }
    }

    // A = ||x||^2: strict sequential scalar, separate mul + add (XLA reduce order).
    float A = 0.f;
    #pragma unroll
    for (int k = 0; k < D; k++) A = __fadd_rn(A, __fmul_rn(x[k], x[k]));

    float best = __int_as_float(0x7f800000);   // +inf
    int bidx = 0;

    for (int t = 0; t < K_CODES; t += TILE) {
        __syncthreads();
        // Cooperative tile load from transposed codebook: row k = 128 floats.
        {
            const float4* src = (const float4*)g_cbT;
            float4* dst = (float4*)sCT;
            #pragma unroll
            for (int it = 0; it < (D * TILE / 4) / BLK; it++) {
                int f = threadIdx.x + it * BLK;     // 0..2047 float4s
                int k = f >> 5;                     // 32 float4 per k-row
                int j4 = f & 31;
                dst[f] = src[(k * K_CODES + t) / 4 + j4];
            }
            if (threadIdx.x < TILE) sC2[threadIdx.x] = g_C[t + threadIdx.x];
        }
        __syncthreads();

        // 16 codes per chunk -> 8 independent ffma2 chains; k strictly ascending
        // inside each chain == Eigen gebp dot order. LDS are warp-broadcast.
        for (int jc = 0; jc < TILE; jc += 16) {
            unsigned long long acc[8];
            #pragma unroll
            for (int i = 0; i < 8; i++) acc[i] = 0ull;

            #pragma unroll
            for (int k = 0; k < D; k++) {
                unsigned long long xb = dup2(x[k]);
                const ulonglong2* cr2 = (const ulonglong2*)(sCT + k * TILE + jc);
                #pragma unroll
                for (int i = 0; i < 4; i++) {
                    ulonglong2 u = cr2[i];
                    acc[2 * i]     = ffma2(xb, u.x, acc[2 * i]);
                    acc[2 * i + 1] = ffma2(xb, u.y, acc[2 * i + 1]);
                }
            }

            // d2 = fl(fl(A - fl(2*t)) + C), ascending j, strict < (first-index ties)
            #pragma unroll
            for (int i = 0; i < 8; i++) {
                float t0, t1;
                unpack2(acc[i], t0, t1);
                int j0 = t + jc + 2 * i;
                float d0 = __fadd_rn(__fsub_rn(A, __fmul_rn(2.f, t0)), sC2[jc + 2 * i]);
                float d1 = __fadd_rn(__fsub_rn(A, __fmul_rn(2.f, t1)), sC2[jc + 2 * i + 1]);
                if (d0 < best) { best = d0; bidx = j0; }
                if (d1 < best) { best = d1; bidx = j0 + 1; }
            }
        }
    }

    // Outputs. quantized_ste = fl(x + fl(c - x)) — exact reference replication.
    float lsum = 0.f;
    {
        const float4* cbest = (const float4*)(cb + (size_t)bidx * D);
        float4* oq = (float4*)(d_out + (size_t)row * D);
        #pragma unroll
        for (int i = 0; i < 16; i++) {
            float4 c = __ldg(&cbest[i]);
            float dd0 = __fsub_rn(c.x, x[4 * i]);
            float dd1 = __fsub_rn(c.y, x[4 * i + 1]);
            float dd2 = __fsub_rn(c.z, x[4 * i + 2]);
            float dd3 = __fsub_rn(c.w, x[4 * i + 3]);
            float4 o;
            o.x = __fadd_rn(x[4 * i],     dd0);
            o.y = __fadd_rn(x[4 * i + 1], dd1);
            o.z = __fadd_rn(x[4 * i + 2], dd2);
            o.w = __fadd_rn(x[4 * i + 3], dd3);
            oq[i] = o;
            // loss term: fl((c-x))^2 accumulated (tolerance 1e-3 -> order free)
            lsum += __fmul_rn(dd0, dd0) + __fmul_rn(dd1, dd1)
                  + __fmul_rn(dd2, dd2) + __fmul_rn(dd3, dd3);
        }
        d_out[IDX_OFF + row] = (float)bidx;
    }

    sRed[threadIdx.x] = lsum;
    __syncthreads();
    #pragma unroll
    for (int w = BLK / 2; w > 0; w >>= 1) {
        if (threadIdx.x < w) sRed[threadIdx.x] += sRed[threadIdx.x + w];
        __syncthreads();
    }
    if (threadIdx.x == 0) g_blocksum[blockIdx.x] = sRed[0];
}

// ---- kernel 3: loss = 1.25 * mean((q - x)^2), double-precision final sum ----
__global__ void vq_finalize(float* __restrict__ d_out) {
    __shared__ double s[256];
    double v = 0.0;
    for (int i = threadIdx.x; i < NBLK; i += 256) v += (double)g_blocksum[i];
    s[threadIdx.x] = v;
    __syncthreads();
    #pragma unroll
    for (int w = 128; w > 0; w >>= 1) {
        if (threadIdx.x < w) s[threadIdx.x] += s[threadIdx.x + w];
        __syncthreads();
    }
    if (threadIdx.x == 0)
        d_out[LOSS_OFF] = (float)(1.25 * s[0] / (double)((size_t)N_ROWS * D));
}

extern "C" void kernel_launch(void* const* d_in, const int* in_sizes, int n_in,
                              void* d_out, int out_size) {
    const float* inp = (const float*)d_in[0];   // inputs  [131072, 64]
    const float* cb  = (const float*)d_in[1];   // codebook [1024, 64]
    float* out = (float*)d_out;

    vq_prep<<<(K_CODES + 127) / 128, 128>>>(cb);
    vq_main<<<NBLK, BLK>>>(inp, cb, out);
    vq_finalize<<<1, 256>>>(out);
}

// round 8
// speedup vs baseline: 1.2464x; 1.2464x over previous
#include <cuda_runtime.h>
#include <cstdint>

// inputs [64,2048,64] fp32 -> flat [131072,64]; codebook [1024,64] fp32.
#define N_ROWS   131072
#define D        64
#define K_CODES  1024
#define TILE     128
#define BLK      128
#define ROWS_PER_BLK (2 * BLK)
#define NBLK2    (N_ROWS / ROWS_PER_BLK)   // 512 blocks

// Output: quantized_ste (8388608) | loss (1) | encoding_indices (131072), all fp32
#define LOSS_OFF 8388608
#define IDX_OFF  8388609

__device__ float g_cbT[D * K_CODES];   // transposed codebook [k][j]
__device__ float g_C[K_CODES];         // ||c_j||^2, reference rounding
__device__ float g_blocksum[NBLK2];

// fma.rn.f32x2: two independent exact IEEE fp32 FMAs per issue (lo/hi lanes).
__device__ __forceinline__ unsigned long long ffma2(unsigned long long a,
                                                    unsigned long long b,
                                                    unsigned long long c) {
    unsigned long long d;
    asm("fma.rn.f32x2 %0, %1, %2, %3;" : "=l"(d) : "l"(a), "l"(b), "l"(c));
    return d;
}
__device__ __forceinline__ unsigned long long dup2(float x) {
    unsigned long long d;
    asm("mov.b64 %0, {%1, %1};" : "=l"(d) : "f"(x));
    return d;
}
__device__ __forceinline__ void unpack2(unsigned long long v, float& lo, float& hi) {
    asm("mov.b64 {%0, %1}, %2;" : "=f"(lo), "=f"(hi) : "l"(v));
}

// ---- kernel 1: transpose codebook + ||c||^2 with reference rounding ----
__global__ void vq_prep(const float* __restrict__ cb) {
    int j = blockIdx.x * blockDim.x + threadIdx.x;
    if (j < K_CODES) {
        float s = 0.f;
        #pragma unroll
        for (int k = 0; k < D; k++) {
            float c = cb[j * D + k];
            s = __fadd_rn(s, __fmul_rn(c, c));
            g_cbT[k * K_CODES + j] = c;
        }
        g_C[j] = s;
    }
}

// ---- kernel 2: main VQ. TWO rows per thread (halves smem LDS per row). ----
__global__ void __launch_bounds__(BLK) vq_main(const float* __restrict__ inp,
                                               const float* __restrict__ cb,
                                               float* __restrict__ d_out) {
    __shared__ __align__(16) float sCT[D * TILE];   // 32 KB, layout [k][j]
    __shared__ float sC2[TILE];
    __shared__ float sRed[BLK];

    const int row0 = blockIdx.x * ROWS_PER_BLK + threadIdx.x;
    const int row1 = row0 + BLK;

    // Both rows resident in registers.
    float x0[D], x1[D];
    {
        const float4* r0 = (const float4*)(inp + (size_t)row0 * D);
        const float4* r1 = (const float4*)(inp + (size_t)row1 * D);
        #pragma unroll
        for (int i = 0; i < 16; i++) {
            float4 v = r0[i];
            x0[4 * i] = v.x; x0[4 * i + 1] = v.y; x0[4 * i + 2] = v.z; x0[4 * i + 3] = v.w;
            float4 w = r1[i];
            x1[4 * i] = w.x; x1[4 * i + 1] = w.y; x1[4 * i + 2] = w.z; x1[4 * i + 3] = w.w;
        }
    }

    // A = ||x||^2: strict sequential scalar, separate mul + add (XLA reduce order).
    float A0 = 0.f, A1 = 0.f;
    #pragma unroll
    for (int k = 0; k < D; k++) {
        A0 = __fadd_rn(A0, __fmul_rn(x0[k], x0[k]));
        A1 = __fadd_rn(A1, __fmul_rn(x1[k], x1[k]));
    }

    float best0 = __int_as_float(0x7f800000), best1 = best0;
    int bidx0 = 0, bidx1 = 0;

    for (int t = 0; t < K_CODES; t += TILE) {
        __syncthreads();
        // Cooperative tile load from transposed codebook: row k = 128 floats.
        {
            const float4* src = (const float4*)g_cbT;
            float4* dst = (float4*)sCT;
            #pragma unroll
            for (int it = 0; it < (D * TILE / 4) / BLK; it++) {
                int f = threadIdx.x + it * BLK;     // 0..2047 float4s
                int k = f >> 5;                     // 32 float4 per k-row
                int j4 = f & 31;
                dst[f] = src[(k * K_CODES + t) / 4 + j4];
            }
            if (threadIdx.x < TILE) sC2[threadIdx.x] = g_C[t + threadIdx.x];
        }
        __syncthreads();

        // 16 codes per chunk: 8 ffma2 chains per row, k strictly ascending
        // (bit-exact Eigen gebp dot order per row). LDS are warp-broadcast and
        // each LDS.128 now feeds 16 FFMA2 (both rows).
        for (int jc = 0; jc < TILE; jc += 16) {
            unsigned long long a0[8], a1[8];
            #pragma unroll
            for (int i = 0; i < 8; i++) { a0[i] = 0ull; a1[i] = 0ull; }

            #pragma unroll 8
            for (int k = 0; k < D; k++) {
                unsigned long long xb0 = dup2(x0[k]);
                unsigned long long xb1 = dup2(x1[k]);
                const ulonglong2* cr2 = (const ulonglong2*)(sCT + k * TILE + jc);
                #pragma unroll
                for (int i = 0; i < 4; i++) {
                    ulonglong2 u = cr2[i];
                    a0[2 * i]     = ffma2(xb0, u.x, a0[2 * i]);
                    a0[2 * i + 1] = ffma2(xb0, u.y, a0[2 * i + 1]);
                    a1[2 * i]     = ffma2(xb1, u.x, a1[2 * i]);
                    a1[2 * i + 1] = ffma2(xb1, u.y, a1[2 * i + 1]);
                }
            }

            // d2 = fl(fl(A - fl(2*t)) + C), ascending j, strict < (first-index ties)
            #pragma unroll
            for (int i = 0; i < 8; i++) {
                int j0 = t + jc + 2 * i;
                float c2a = sC2[jc + 2 * i], c2b = sC2[jc + 2 * i + 1];
                float t0, t1;
                unpack2(a0[i], t0, t1);
                float d0 = __fadd_rn(__fsub_rn(A0, __fmul_rn(2.f, t0)), c2a);
                float d1 = __fadd_rn(__fsub_rn(A0, __fmul_rn(2.f, t1)), c2b);
                if (d0 < best0) { best0 = d0; bidx0 = j0; }
                if (d1 < best0) { best0 = d1; bidx0 = j0 + 1; }
                unpack2(a1[i], t0, t1);
                float e0 = __fadd_rn(__fsub_rn(A1, __fmul_rn(2.f, t0)), c2a);
                float e1 = __fadd_rn(__fsub_rn(A1, __fmul_rn(2.f, t1)), c2b);
                if (e0 < best1) { best1 = e0; bidx1 = j0; }
                if (e1 < best1) { best1 = e1; bidx1 = j0 + 1; }
            }
        }
    }

    // Outputs. quantized_ste = fl(x + fl(c - x)) — exact reference replication.
    float lsum = 0.f;
    {
        const float4* cb0 = (const float4*)(cb + (size_t)bidx0 * D);
        const float4* cb1 = (const float4*)(cb + (size_t)bidx1 * D);
        float4* oq0 = (float4*)(d_out + (size_t)row0 * D);
        float4* oq1 = (float4*)(d_out + (size_t)row1 * D);
        #pragma unroll
        for (int i = 0; i < 16; i++) {
            float4 c = __ldg(&cb0[i]);
            float dd0 = __fsub_rn(c.x, x0[4 * i]);
            float dd1 = __fsub_rn(c.y, x0[4 * i + 1]);
            float dd2 = __fsub_rn(c.z, x0[4 * i + 2]);
            float dd3 = __fsub_rn(c.w, x0[4 * i + 3]);
            float4 o;
            o.x = __fadd_rn(x0[4 * i],     dd0);
            o.y = __fadd_rn(x0[4 * i + 1], dd1);
            o.z = __fadd_rn(x0[4 * i + 2], dd2);
            o.w = __fadd_rn(x0[4 * i + 3], dd3);
            oq0[i] = o;
            lsum += __fmul_rn(dd0, dd0) + __fmul_rn(dd1, dd1)
                  + __fmul_rn(dd2, dd2) + __fmul_rn(dd3, dd3);
        }
        #pragma unroll
        for (int i = 0; i < 16; i++) {
            float4 c = __ldg(&cb1[i]);
            float dd0 = __fsub_rn(c.x, x1[4 * i]);
            float dd1 = __fsub_rn(c.y, x1[4 * i + 1]);
            float dd2 = __fsub_rn(c.z, x1[4 * i + 2]);
            float dd3 = __fsub_rn(c.w, x1[4 * i + 3]);
            float4 o;
            o.x = __fadd_rn(x1[4 * i],     dd0);
            o.y = __fadd_rn(x1[4 * i + 1], dd1);
            o.z = __fadd_rn(x1[4 * i + 2], dd2);
            o.w = __fadd_rn(x1[4 * i + 3], dd3);
            oq1[i] = o;
            lsum += __fmul_rn(dd0, dd0) + __fmul_rn(dd1, dd1)
                  + __fmul_rn(dd2, dd2) + __fmul_rn(dd3, dd3);
        }
        d_out[IDX_OFF + row0] = (float)bidx0;
        d_out[IDX_OFF + row1] = (float)bidx1;
    }

    sRed[threadIdx.x] = lsum;
    __syncthreads();
    #pragma unroll
    for (int w = BLK / 2; w > 0; w >>= 1) {
        if (threadIdx.x < w) sRed[threadIdx.x] += sRed[threadIdx.x + w];
        __syncthreads();
    }
    if (threadIdx.x == 0) g_blocksum[blockIdx.x] = sRed[0];
}

// ---- kernel 3: loss = 1.25 * mean((q - x)^2), double-precision final sum ----
__global__ void vq_finalize(float* __restrict__ d_out) {
    __shared__ double s[256];
    double v = 0.0;
    for (int i = threadIdx.x; i < NBLK2; i += 256) v += (double)g_blocksum[i];
    s[threadIdx.x] = v;
    __syncthreads();
    #pragma unroll
    for (int w = 128; w > 0; w >>= 1) {
        if (threadIdx.x < w) s[threadIdx.x] += s[threadIdx.x + w];
        __syncthreads();
    }
    if (threadIdx.x == 0)
        d_out[LOSS_OFF] = (float)(1.25 * s[0] / (double)((size_t)N_ROWS * D));
}

extern "C" void kernel_launch(void* const* d_in, const int* in_sizes, int n_in,
                              void* d_out, int out_size) {
    const float* inp = (const float*)d_in[0];   // inputs  [131072, 64]
    const float* cb  = (const float*)d_in[1];   // codebook [1024, 64]
    float* out = (float*)d_out;

    vq_prep<<<(K_CODES + 127) / 128, 128>>>(cb);
    vq_main<<<NBLK2, BLK>>>(inp, cb, out);
    vq_finalize<<<1, 256>>>(out);
}

// round 15
// speedup vs baseline: 2.0596x; 1.6524x over previous
#include <cuda_runtime.h>
#include <cuda_bf16.h>
#include <cstdint>

// inputs [64,2048,64] fp32 -> flat [131072,64]; codebook [1024,64] fp32.
#define N_ROWS   131072
#define D        64
#define K_CODES  1024
#define MTILE    128
#define BLK2     256
#define GRID2    (N_ROWS / MTILE)      // 1024
#define NTILES   (K_CODES / 8)         // 128

#define EX_BLK   256
#define EX_GRID  (N_ROWS / EX_BLK)     // 512

// Output: quantized_ste (8388608) | loss (1) | encoding_indices (131072), fp32
#define LOSS_OFF 8388608
#define IDX_OFF  8388609

#define APAD     144                   // A smem row pitch (bytes): conflict-free

__device__ float g_C[K_CODES];                 // ||c||^2, reference rounding
__device__ uint4 g_bfrag[NTILES * 4 * 32];     // fragment-ordered bf16 hi/lo B
__device__ int   g_cnt[N_ROWS];                // 0 = use slots, -1 = full scan
__device__ int   g_cidx[N_ROWS * 16];          // candidate slots (sentinel INT_MAX)
__device__ float g_blocksum[EX_GRID];

__device__ __forceinline__ uint32_t packbf(__nv_bfloat16 a, __nv_bfloat16 b) {
    return (uint32_t)__bfloat16_as_ushort(a) | ((uint32_t)__bfloat16_as_ushort(b) << 16);
}
__device__ __forceinline__ __nv_bfloat16 bfhi(float x) { return __float2bfloat16(x); }
__device__ __forceinline__ __nv_bfloat16 bflo(float x, __nv_bfloat16 h) {
    return __float2bfloat16(__fsub_rn(x, __bfloat162float(h)));
}

// mma.sync m16n8k16 bf16 -> f32 (HMMA; supported on plain sm_103 target)
__device__ __forceinline__ void mma16816(float& c0, float& c1, float& c2, float& c3,
                                         uint32_t a0, uint32_t a1, uint32_t a2, uint32_t a3,
                                         uint32_t b0, uint32_t b1) {
    asm volatile("mma.sync.aligned.m16n8k16.row.col.f32.bf16.bf16.f32 "
                 "{%0,%1,%2,%3}, {%4,%5,%6,%7}, {%8,%9}, {%0,%1,%2,%3};"
                 : "+f"(c0), "+f"(c1), "+f"(c2), "+f"(c3)
                 : "r"(a0), "r"(a1), "r"(a2), "r"(a3), "r"(b0), "r"(b1));
}

__device__ __forceinline__ void ins4(float u, int j,
                                     float& v0, float& v1, float& v2, float& v3,
                                     int& i0, int& i1, int& i2, int& i3) {
    if (u < v3) {
        if (u < v1) {
            if (u < v0) { v3=v2;i3=i2; v2=v1;i2=i1; v1=v0;i1=i0; v0=u;i0=j; }
            else        { v3=v2;i3=i2; v2=v1;i2=i1; v1=u;i1=j; }
        } else {
            if (u < v2) { v3=v2;i3=i2; v2=u;i2=j; }
            else        { v3=u;i3=j; }
        }
    }
}

// ---- kernel 1: ||c||^2 (reference rounding) + fragment-ordered bf16 B -----
__global__ void vq_prep(const float* __restrict__ cb) {
    int e = blockIdx.x * blockDim.x + threadIdx.x;      // 0..16383
    if (e < K_CODES) {
        float s = 0.f;
        #pragma unroll
        for (int k = 0; k < D; k++) {
            float c = cb[e * D + k];
            s = __fadd_rn(s, __fmul_rn(c, c));
        }
        g_C[e] = s;
    }
    // entry (jt, ks, lane): n = lane>>2, kp = lane&3; code = jt*8+n
    int lane = e & 31, ks = (e >> 5) & 3, jt = e >> 7;
    int n = lane >> 2, kp = lane & 3;
    int code = jt * 8 + n;
    int kb = ks * 16 + kp * 2;
    float c0 = cb[code * D + kb],     c1 = cb[code * D + kb + 1];
    float c2 = cb[code * D + kb + 8], c3 = cb[code * D + kb + 9];
    __nv_bfloat16 h0 = bfhi(c0), h1 = bfhi(c1), h2 = bfhi(c2), h3 = bfhi(c3);
    uint4 ent;
    ent.x = packbf(h0, h1);
    ent.y = packbf(h2, h3);
    ent.z = packbf(bflo(c0, h0), bflo(c1, h1));
    ent.w = packbf(bflo(c2, h2), bflo(c3, h3));
    g_bfrag[e] = ent;
}

// ---- kernel 2: HMMA bf16-split score GEMM + margin candidates --------------
__global__ void __launch_bounds__(BLK2, 2) vq_mma(const float* __restrict__ inp) {
    __shared__ __align__(16) unsigned char sA[2 * 128 * APAD];  // hi | lo tiles
    __shared__ float sC2[K_CODES];
    __shared__ float sAn[MTILE];

    const int tid = threadIdx.x;
    const int ctaRow = blockIdx.x * MTILE;

    // Phase 1: threads 0-127 build the A tile (bf16 hi/lo) + exact sequential
    // ||x||^2; threads 128-255 stage g_C into smem.
    if (tid < 128) {
        const float4* xr = (const float4*)(inp + (size_t)(ctaRow + tid) * D);
        float A = 0.f;
        unsigned char* rh = sA + tid * APAD;
        unsigned char* rl = sA + 128 * APAD + tid * APAD;
        #pragma unroll
        for (int i = 0; i < 16; i++) {
            float4 v = xr[i];
            A = __fadd_rn(A, __fmul_rn(v.x, v.x));
            A = __fadd_rn(A, __fmul_rn(v.y, v.y));
            A = __fadd_rn(A, __fmul_rn(v.z, v.z));
            A = __fadd_rn(A, __fmul_rn(v.w, v.w));
            __nv_bfloat16 h0 = bfhi(v.x), h1 = bfhi(v.y), h2 = bfhi(v.z), h3 = bfhi(v.w);
            *(uint32_t*)(rh + i * 8)     = packbf(h0, h1);
            *(uint32_t*)(rh + i * 8 + 4) = packbf(h2, h3);
            *(uint32_t*)(rl + i * 8)     = packbf(bflo(v.x, h0), bflo(v.y, h1));
            *(uint32_t*)(rl + i * 8 + 4) = packbf(bflo(v.z, h2), bflo(v.w, h3));
        }
        sAn[tid] = A;
    } else {
        int t = tid - 128;
        #pragma unroll
        for (int i = 0; i < 8; i++) sC2[t * 8 + i] = g_C[t * 8 + i];
    }
    __syncthreads();

    // Phase 2: A fragments for all 4 k-steps, hi and lo, resident in registers.
    const int wid = tid >> 5, lane = tid & 31;
    const int mb = wid * 16;
    const int r = lane >> 2, kp = lane & 3;
    uint32_t ah[4][4], al[4][4];
    #pragma unroll
    for (int ks = 0; ks < 4; ks++) {
        uint32_t o = (uint32_t)(mb + r) * APAD + ks * 32 + kp * 4;
        ah[ks][0] = *(const uint32_t*)(sA + o);
        ah[ks][1] = *(const uint32_t*)(sA + o + 8 * APAD);
        ah[ks][2] = *(const uint32_t*)(sA + o + 16);
        ah[ks][3] = *(const uint32_t*)(sA + o + 8 * APAD + 16);
        uint32_t ol = o + 128 * APAD;
        al[ks][0] = *(const uint32_t*)(sA + ol);
        al[ks][1] = *(const uint32_t*)(sA + ol + 8 * APAD);
        al[ks][2] = *(const uint32_t*)(sA + ol + 16);
        al[ks][3] = *(const uint32_t*)(sA + ol + 8 * APAD + 16);
    }

    const float INF = __int_as_float(0x7f800000);
    float v0 = INF, v1 = INF, v2 = INF, v3 = INF;      // rows mb+r
    int   i0 = 0, i1 = 0, i2 = 0, i3 = 0;
    float w0 = INF, w1 = INF, w2 = INF, w3 = INF;      // rows mb+r+8
    int   k0 = 0, k1 = 0, k2 = 0, k3 = 0;

    // Phase 3: stream fragment-ordered B from L2 with register double-buffer.
    const uint4* bf = g_bfrag;
    uint4 bc0 = __ldg(bf + 0 * 32 + lane);
    uint4 bc1 = __ldg(bf + 1 * 32 + lane);
    uint4 bc2 = __ldg(bf + 2 * 32 + lane);
    uint4 bc3 = __ldg(bf + 3 * 32 + lane);

    #pragma unroll 2
    for (int jt = 0; jt < NTILES; jt++) {
        int nt = (jt < NTILES - 1) ? jt + 1 : jt;
        uint4 bn0 = __ldg(bf + (nt * 4 + 0) * 32 + lane);
        uint4 bn1 = __ldg(bf + (nt * 4 + 1) * 32 + lane);
        uint4 bn2 = __ldg(bf + (nt * 4 + 2) * 32 + lane);
        uint4 bn3 = __ldg(bf + (nt * 4 + 3) * 32 + lane);

        float c0 = 0.f, c1 = 0.f, c2 = 0.f, c3 = 0.f;
        mma16816(c0,c1,c2,c3, ah[0][0],ah[0][1],ah[0][2],ah[0][3], bc0.x, bc0.y);
        mma16816(c0,c1,c2,c3, ah[0][0],ah[0][1],ah[0][2],ah[0][3], bc0.z, bc0.w);
        mma16816(c0,c1,c2,c3, al[0][0],al[0][1],al[0][2],al[0][3], bc0.x, bc0.y);
        mma16816(c0,c1,c2,c3, ah[1][0],ah[1][1],ah[1][2],ah[1][3], bc1.x, bc1.y);
        mma16816(c0,c1,c2,c3, ah[1][0],ah[1][1],ah[1][2],ah[1][3], bc1.z, bc1.w);
        mma16816(c0,c1,c2,c3, al[1][0],al[1][1],al[1][2],al[1][3], bc1.x, bc1.y);
        mma16816(c0,c1,c2,c3, ah[2][0],ah[2][1],ah[2][2],ah[2][3], bc2.x, bc2.y);
        mma16816(c0,c1,c2,c3, ah[2][0],ah[2][1],ah[2][2],ah[2][3], bc2.z, bc2.w);
        mma16816(c0,c1,c2,c3, al[2][0],al[2][1],al[2][2],al[2][3], bc2.x, bc2.y);
        mma16816(c0,c1,c2,c3, ah[3][0],ah[3][1],ah[3][2],ah[3][3], bc3.x, bc3.y);
        mma16816(c0,c1,c2,c3, ah[3][0],ah[3][1],ah[3][2],ah[3][3], bc3.z, bc3.w);
        mma16816(c0,c1,c2,c3, al[3][0],al[3][1],al[3][2],al[3][3], bc3.x, bc3.y);

        // accum layout: rows (mb+r, mb+r+8), cols j0 = jt*8 + kp*2 (+1)
        int j0 = jt * 8 + kp * 2;
        float2 Cp = *(const float2*)(sC2 + j0);
        float u0 = fmaf(-2.f, c0, Cp.x);
        float u1 = fmaf(-2.f, c1, Cp.y);
        float u2 = fmaf(-2.f, c2, Cp.x);
        float u3 = fmaf(-2.f, c3, Cp.y);
        ins4(u0, j0,     v0, v1, v2, v3, i0, i1, i2, i3);
        ins4(u1, j0 + 1, v0, v1, v2, v3, i0, i1, i2, i3);
        ins4(u2, j0,     w0, w1, w2, w3, k0, k1, k2, k3);
        ins4(u3, j0 + 1, w0, w1, w2, w3, k0, k1, k2, k3);

        bc0 = bn0; bc1 = bn1; bc2 = bn2; bc3 = bn3;
    }

    // Phase 4: per-row merge across the 4 quad lanes; write candidate slots.
    #pragma unroll
    for (int half = 0; half < 2; half++) {
        float a0 = half ? w0 : v0, a1 = half ? w1 : v1;
        float a2 = half ? w2 : v2, a3 = half ? w3 : v3;
        int   b0 = half ? k0 : i0, b1 = half ? k1 : i1;
        int   b2 = half ? k2 : i2, b3 = half ? k3 : i3;
        int rowLocal = mb + r + half * 8;
        float Ar = sAn[rowLocal];
        float vm = a0;
        vm = fminf(vm, __shfl_xor_sync(0xffffffffu, vm, 1));
        vm = fminf(vm, __shfl_xor_sync(0xffffffffu, vm, 2));
        float th = vm + fmaf(Ar, 6.0e-7f, 6.0e-6f);
        int fl = (a3 <= th) ? 1 : 0;
        fl |= __shfl_xor_sync(0xffffffffu, fl, 1);
        fl |= __shfl_xor_sync(0xffffffffu, fl, 2);
        int grow = ctaRow + rowLocal;
        int base = grow * 16 + kp * 4;
        g_cidx[base + 0] = (a0 <= th) ? b0 : 0x7fffffff;
        g_cidx[base + 1] = (a1 <= th) ? b1 : 0x7fffffff;
        g_cidx[base + 2] = (a2 <= th) ? b2 : 0x7fffffff;
        g_cidx[base + 3] = (a3 <= th) ? b3 : 0x7fffffff;
        if (kp == 0) g_cnt[grow] = fl ? -1 : 0;
    }
}

// ---- kernel 3: bit-exact recheck + all outputs -----------------------------
__global__ void __launch_bounds__(EX_BLK) vq_exact(const float* __restrict__ inp,
                                                   const float* __restrict__ cb,
                                                   float* __restrict__ d_out) {
    __shared__ float sRed[EX_BLK];
    const int row = blockIdx.x * EX_BLK + threadIdx.x;

    float x[D];
    {
        const float4* xr = (const float4*)(inp + (size_t)row * D);
        #pragma unroll
        for (int i = 0; i < 16; i++) {
            float4 v = xr[i];
            x[4 * i] = v.x; x[4 * i + 1] = v.y; x[4 * i + 2] = v.z; x[4 * i + 3] = v.w;
        }
    }
    float A = 0.f;
    #pragma unroll
    for (int k = 0; k < D; k++) A = __fadd_rn(A, __fmul_rn(x[k], x[k]));

    float best = __int_as_float(0x7f800000);
    int bidx = 0x7fffffff;

    if (g_cnt[row] == 0) {
        #pragma unroll 1
        for (int s = 0; s < 16; s++) {
            int j = g_cidx[row * 16 + s];
            if (j < K_CODES) {
                float t = 0.f;
                #pragma unroll
                for (int k = 0; k < D; k++)
                    t = __fmaf_rn(x[k], __ldg(&cb[j * D + k]), t);
                float dd = __fadd_rn(__fsub_rn(A, __fmul_rn(2.f, t)), g_C[j]);
                if (dd < best || (dd == best && j < bidx)) { best = dd; bidx = j; }
            }
        }
    } else {   // provably-correct rare fallback: full exact scan
        for (int j = 0; j < K_CODES; j++) {
            float t = 0.f;
            #pragma unroll
            for (int k = 0; k < D; k++)
                t = __fmaf_rn(x[k], __ldg(&cb[j * D + k]), t);
            float dd = __fadd_rn(__fsub_rn(A, __fmul_rn(2.f, t)), g_C[j]);
            if (dd < best) { best = dd; bidx = j; }
        }
    }

    // outputs: quantized_ste = fl(x + fl(c - x)), idx, loss partial
    float lsum = 0.f;
    {
        const float4* cbest = (const float4*)(cb + (size_t)bidx * D);
        float4* oq = (float4*)(d_out + (size_t)row * D);
        #pragma unroll
        for (int i = 0; i < 16; i++) {
            float4 c = __ldg(&cbest[i]);
            float dd0 = __fsub_rn(c.x, x[4 * i]);
            float dd1 = __fsub_rn(c.y, x[4 * i + 1]);
            float dd2 = __fsub_rn(c.z, x[4 * i + 2]);
            float dd3 = __fsub_rn(c.w, x[4 * i + 3]);
            float4 o;
            o.x = __fadd_rn(x[4 * i],     dd0);
            o.y = __fadd_rn(x[4 * i + 1], dd1);
            o.z = __fadd_rn(x[4 * i + 2], dd2);
            o.w = __fadd_rn(x[4 * i + 3], dd3);
            oq[i] = o;
            lsum += __fmul_rn(dd0, dd0) + __fmul_rn(dd1, dd1)
                  + __fmul_rn(dd2, dd2) + __fmul_rn(dd3, dd3);
        }
        d_out[IDX_OFF + row] = (float)bidx;
    }

    sRed[threadIdx.x] = lsum;
    __syncthreads();
    #pragma unroll
    for (int w = EX_BLK / 2; w > 0; w >>= 1) {
        if (threadIdx.x < w) sRed[threadIdx.x] += sRed[threadIdx.x + w];
        __syncthreads();
    }
    if (threadIdx.x == 0) g_blocksum[blockIdx.x] = sRed[0];
}

// ---- kernel 4: loss = 1.25 * mean((q - x)^2) -------------------------------
__global__ void vq_finalize(float* __restrict__ d_out) {
    __shared__ double s[256];
    double v = 0.0;
    for (int i = threadIdx.x; i < EX_GRID; i += 256) v += (double)g_blocksum[i];
    s[threadIdx.x] = v;
    __syncthreads();
    #pragma unroll
    for (int w = 128; w > 0; w >>= 1) {
        if (threadIdx.x < w) s[threadIdx.x] += s[threadIdx.x + w];
        __syncthreads();
    }
    if (threadIdx.x == 0)
        d_out[LOSS_OFF] = (float)(1.25 * s[0] / (double)((size_t)N_ROWS * D));
}

extern "C" void kernel_launch(void* const* d_in, const int* in_sizes, int n_in,
                              void* d_out, int out_size) {
    const float* inp = (const float*)d_in[0];
    const float* cb  = (const float*)d_in[1];
    float* out = (float*)d_out;

    vq_prep<<<64, 256>>>(cb);
    vq_mma<<<GRID2, BLK2>>>(inp);
    vq_exact<<<EX_GRID, EX_BLK>>>(inp, cb, out);
    vq_finalize<<<1, 256>>>(out);
}